// round 1
// baseline (speedup 1.0000x reference)
#include <cuda_runtime.h>
#include <math.h>

// Problem constants
#define BB 4
#define EE 8
#define NTOK 1024
#define DD 1024
#define HH 4096
#define MM 4096   // B*N tokens per expert

// fp32 scratch for hidden activations: [E][M][H] = 8*4096*4096 floats = 512 MiB
__device__ float g_h[(size_t)EE * MM * HH];

__device__ __forceinline__ float gelu_tanh(float v) {
    // jax.nn.gelu default (approximate=True): 0.5*v*(1+tanh(sqrt(2/pi)*(v+0.044715 v^3)))
    const float c0 = 0.7978845608028654f;
    const float c1 = 0.044715f;
    float u = c0 * (v + c1 * v * v * v);
    return 0.5f * v * (1.0f + tanhf(u));
}

// Row offset into the (B,E,N,D)-shaped tensor for "token row m" of expert e.
// m in [0, B*N): b = m>>10, n = m&1023  (NTOK = 1024)
__device__ __forceinline__ size_t xrow_off(int m, int e) {
    return ((size_t)(m >> 10) * EE + e) * ((size_t)NTOK * DD) + (size_t)(m & 1023) * DD;
}

// Tiled fp32 GEMM: C[e] = op(A[e] @ B[e] + bias[e])
//   A: [M=4096, K] rows either indexed (x layout) or contiguous per expert
//   B: [K, NC] row-major per expert (w1/w2 layouts are exactly this)
//   C: [M, NC] either indexed (out layout) or contiguous per expert
// Tile: 128x128x16, 256 threads, 8x8 microtile per thread.
template<int K, int NC, bool A_IDX, bool C_IDX, bool GELU>
__global__ __launch_bounds__(256)
void gemm_kernel(const float* __restrict__ A,
                 const float* __restrict__ Bm,
                 const float* __restrict__ bias,
                 float* __restrict__ C)
{
    const int e  = blockIdx.z;
    const int m0 = blockIdx.y * 128;
    const int n0 = blockIdx.x * 128;
    const int tx = threadIdx.x;   // 0..15
    const int ty = threadIdx.y;   // 0..15
    const int tid = ty * 16 + tx;

    __shared__ float As[16][132];  // transposed: As[k][m]
    __shared__ float Bs[16][132];  // Bs[k][n]

    float acc[8][8];
    #pragma unroll
    for (int i = 0; i < 8; i++)
        #pragma unroll
        for (int j = 0; j < 8; j++)
            acc[i][j] = 0.0f;

    for (int k0 = 0; k0 < K; k0 += 16) {
        // ---- load A tile: 128 rows x 16 k  (512 float4, 2 per thread) ----
        #pragma unroll
        for (int t = 0; t < 2; t++) {
            int q   = tid + t * 256;
            int row = q >> 2;              // 4 float4 per row of 16
            int kq  = (q & 3) << 2;
            int m   = m0 + row;
            size_t aoff;
            if (A_IDX) aoff = xrow_off(m, e);
            else       aoff = ((size_t)e * MM + m) * (size_t)K;
            float4 v = *(const float4*)(A + aoff + k0 + kq);
            As[kq + 0][row] = v.x;
            As[kq + 1][row] = v.y;
            As[kq + 2][row] = v.z;
            As[kq + 3][row] = v.w;
        }
        // ---- load B tile: 16 k x 128 n  (512 float4, 2 per thread) ----
        #pragma unroll
        for (int t = 0; t < 2; t++) {
            int q  = tid + t * 256;
            int kr = q >> 5;               // 32 float4 per row of 128
            int nc = (q & 31) << 2;
            size_t boff = ((size_t)e * K + (size_t)(k0 + kr)) * (size_t)NC + n0 + nc;
            *(float4*)&Bs[kr][nc] = *(const float4*)(Bm + boff);
        }
        __syncthreads();

        // ---- compute ----
        #pragma unroll
        for (int kk = 0; kk < 16; kk++) {
            float4 a0 = *(const float4*)&As[kk][ty * 8];
            float4 a1 = *(const float4*)&As[kk][ty * 8 + 4];
            float4 b0 = *(const float4*)&Bs[kk][tx * 8];
            float4 b1 = *(const float4*)&Bs[kk][tx * 8 + 4];
            float a[8] = {a0.x, a0.y, a0.z, a0.w, a1.x, a1.y, a1.z, a1.w};
            float b[8] = {b0.x, b0.y, b0.z, b0.w, b1.x, b1.y, b1.z, b1.w};
            #pragma unroll
            for (int i = 0; i < 8; i++)
                #pragma unroll
                for (int j = 0; j < 8; j++)
                    acc[i][j] = fmaf(a[i], b[j], acc[i][j]);
        }
        __syncthreads();
    }

    // ---- epilogue: bias (+ gelu) + store ----
    #pragma unroll
    for (int i = 0; i < 8; i++) {
        int m = m0 + ty * 8 + i;
        size_t coff;
        if (C_IDX) coff = xrow_off(m, e);
        else       coff = ((size_t)e * MM + m) * (size_t)NC;
        #pragma unroll
        for (int j = 0; j < 8; j += 4) {
            int n = n0 + tx * 8 + j;
            float4 bv = *(const float4*)(bias + (size_t)e * NC + n);
            float4 r;
            r.x = acc[i][j + 0] + bv.x;
            r.y = acc[i][j + 1] + bv.y;
            r.z = acc[i][j + 2] + bv.z;
            r.w = acc[i][j + 3] + bv.w;
            if (GELU) {
                r.x = gelu_tanh(r.x);
                r.y = gelu_tanh(r.y);
                r.z = gelu_tanh(r.z);
                r.w = gelu_tanh(r.w);
            }
            *(float4*)(C + coff + n) = r;
        }
    }
}

extern "C" void kernel_launch(void* const* d_in, const int* in_sizes, int n_in,
                              void* d_out, int out_size)
{
    const float* x  = (const float*)d_in[0];   // (B,E,N,D)
    const float* w1 = (const float*)d_in[1];   // (E,D,H)
    const float* b1 = (const float*)d_in[2];   // (E,H)
    const float* w2 = (const float*)d_in[3];   // (E,H,D)
    const float* b2 = (const float*)d_in[4];   // (E,D)
    float* out = (float*)d_out;                // (B,E,N,D)

    float* h = nullptr;
    cudaGetSymbolAddress((void**)&h, g_h);

    dim3 block(16, 16);
    dim3 grid1(HH / 128, MM / 128, EE);   // 32 x 32 x 8
    dim3 grid2(DD / 128, MM / 128, EE);   //  8 x 32 x 8

    // h = gelu(x @ w1 + b1)    (A = x indexed layout, C = contiguous scratch)
    gemm_kernel<DD, HH, true,  false, true ><<<grid1, block>>>(x, w1, b1, h);
    // out = h @ w2 + b2        (A = contiguous scratch, C = out indexed layout)
    gemm_kernel<HH, DD, false, true,  false><<<grid2, block>>>(h, w2, b2, out);
}

// round 3
// speedup vs baseline: 3.1021x; 3.1021x over previous
#include <cuda_runtime.h>
#include <math.h>
#include <stdint.h>

// ---------------- problem constants ----------------
#define BBATCH 4
#define EE 8
#define NTOK 1024
#define DD 1024
#define HH 4096
#define MMTOK 4096          // B*N rows per expert

// ---------------- tile config ----------------
#define BM 128
#define BN 128
#define BK 16
#define KPAD 20             // A smem row stride (floats): conflict-free fragment loads
#define NPAD 136            // W smem row stride (floats): conflict-free fragment loads

// ---------------- device scratch (tf32-rounded copies + hidden acts) ----------------
__device__ __align__(1024) float g_h  [(size_t)EE * MMTOK * HH];          // 512 MiB
__device__ __align__(1024) float g_xr [(size_t)BBATCH * EE * NTOK * DD];  // 128 MiB
__device__ __align__(1024) float g_w1r[(size_t)EE * DD * HH];             // 128 MiB
__device__ __align__(1024) float g_w2r[(size_t)EE * HH * DD];             // 128 MiB

// ---------------- helpers ----------------
__device__ __forceinline__ float rna_tf32(float x) {
    uint32_t r;
    asm("cvt.rna.tf32.f32 %0, %1;" : "=r"(r) : "f"(x));
    return __uint_as_float(r);
}
__device__ __forceinline__ float gelu_tanh(float v) {
    const float c0 = 0.7978845608028654f;
    const float c1 = 0.044715f;
    float u = c0 * (v + c1 * v * v * v);
    return 0.5f * v * (1.0f + tanhf(u));
}
__device__ __forceinline__ size_t xrow_off(int m, int e) {
    // row m (of B*N) of expert e inside the (B,E,N,D) tensor
    return ((size_t)((m >> 10) * EE + e) * NTOK + (size_t)(m & (NTOK - 1))) * DD;
}
__device__ __forceinline__ void cp16(uint32_t smem_dst, const float* gsrc) {
    asm volatile("cp.async.cg.shared.global [%0], [%1], 16;" :: "r"(smem_dst), "l"(gsrc));
}
__device__ __forceinline__ void cp_commit() { asm volatile("cp.async.commit_group;"); }
template<int N> __device__ __forceinline__ void cp_wait() {
    asm volatile("cp.async.wait_group %0;" :: "n"(N));
}
__device__ __forceinline__ void mma_tf32(float* c, const float* a, const float* b) {
    asm volatile(
        "mma.sync.aligned.m16n8k8.row.col.f32.tf32.tf32.f32 "
        "{%0,%1,%2,%3}, {%4,%5,%6,%7}, {%8,%9}, {%0,%1,%2,%3};"
        : "+f"(c[0]), "+f"(c[1]), "+f"(c[2]), "+f"(c[3])
        : "r"(__float_as_uint(a[0])), "r"(__float_as_uint(a[1])),
          "r"(__float_as_uint(a[2])), "r"(__float_as_uint(a[3])),
          "r"(__float_as_uint(b[0])), "r"(__float_as_uint(b[1])));
}

// ---------------- prep: tf32-round (rna) elementwise copy ----------------
__global__ __launch_bounds__(256) void round_copy(const float* __restrict__ in,
                                                  float* __restrict__ out) {
    size_t i = (size_t)blockIdx.x * blockDim.x + threadIdx.x;
    float4 v = ((const float4*)in)[i];
    v.x = rna_tf32(v.x); v.y = rna_tf32(v.y); v.z = rna_tf32(v.z); v.w = rna_tf32(v.w);
    ((float4*)out)[i] = v;
}

// ---------------- main GEMM ----------------
// C[e] = act(A[e] @ W[e] + bias[e])
//   A: [M=4096, K] K-major fp32 (tf32-rounded). A_IDX -> x layout, else contiguous.
//   W: [K, NC] row-major per expert (tf32-rounded).
//   C: [M, NC]; C_IDX -> (B,E,N,D) layout, else contiguous.
template<int K, int NC, bool A_IDX, bool C_IDX, bool GELU>
__global__ void __launch_bounds__(256, 2) ffn_gemm(
    const float* __restrict__ A,
    const float* __restrict__ W,
    const float* __restrict__ bias,
    float* __restrict__ C)
{
    __shared__ float As[2][BM * KPAD];     // [m][k], kpad=20
    __shared__ float Ws[2][BK * NPAD];     // [k][n], npad=136

    const int tid  = threadIdx.x;
    const int lane = tid & 31;
    const int wid  = tid >> 5;
    const int wm   = wid >> 2;             // 0..1
    const int wn   = wid & 3;              // 0..3
    const int qr   = lane >> 2;            // 0..7
    const int qc   = lane & 3;             // 0..3

    const int e  = blockIdx.z;
    const int m0 = blockIdx.y * BM;
    const int n0 = blockIdx.x * BN;

    // ---- per-thread cp.async source/dest (2 chunks of A, 2 of W per stage) ----
    // A: 512 chunks of 16B: chunk q -> row=q>>2, kc=(q&3)*4
    // W: 512 chunks of 16B: chunk q -> krow=q>>5, nc=(q&31)*4
    int aq0 = tid, aq1 = tid + 256;
    int ar0 = aq0 >> 2, ak0 = (aq0 & 3) << 2;
    int ar1 = aq1 >> 2, ak1 = (aq1 & 3) << 2;
    size_t aoff0, aoff1;
    if (A_IDX) { aoff0 = xrow_off(m0 + ar0, e); aoff1 = xrow_off(m0 + ar1, e); }
    else       { aoff0 = ((size_t)e * MMTOK + m0 + ar0) * (size_t)K;
                 aoff1 = ((size_t)e * MMTOK + m0 + ar1) * (size_t)K; }
    int wk0 = tid >> 5,        wn0 = (tid & 31) << 2;
    int wk1 = (tid + 256) >> 5, wn1 = ((tid + 256) & 31) << 2;
    const float* wbase = W + (size_t)e * K * NC + n0;

    uint32_t sAs0 = (uint32_t)__cvta_generic_to_shared(&As[0][0]);
    uint32_t sAs1 = (uint32_t)__cvta_generic_to_shared(&As[1][0]);
    uint32_t sWs0 = (uint32_t)__cvta_generic_to_shared(&Ws[0][0]);
    uint32_t sWs1 = (uint32_t)__cvta_generic_to_shared(&Ws[1][0]);

    float acc[4][4][4];
    #pragma unroll
    for (int i = 0; i < 4; i++)
        #pragma unroll
        for (int j = 0; j < 4; j++)
            #pragma unroll
            for (int r = 0; r < 4; r++) acc[i][j][r] = 0.0f;

    constexpr int KCH = K / BK;

    // prefetch stage 0
    {
        cp16(sAs0 + (ar0 * KPAD + ak0) * 4, A + aoff0 + ak0);
        cp16(sAs0 + (ar1 * KPAD + ak1) * 4, A + aoff1 + ak1);
        cp16(sWs0 + (wk0 * NPAD + wn0) * 4, wbase + (size_t)wk0 * NC + wn0);
        cp16(sWs0 + (wk1 * NPAD + wn1) * 4, wbase + (size_t)wk1 * NC + wn1);
        cp_commit();
    }

    #pragma unroll 1
    for (int c = 0; c < KCH; c++) {
        const int cur = c & 1;
        if (c + 1 < KCH) {
            const int nxt = cur ^ 1;
            const int k0 = (c + 1) * BK;
            uint32_t sa = nxt ? sAs1 : sAs0;
            uint32_t sw = nxt ? sWs1 : sWs0;
            cp16(sa + (ar0 * KPAD + ak0) * 4, A + aoff0 + k0 + ak0);
            cp16(sa + (ar1 * KPAD + ak1) * 4, A + aoff1 + k0 + ak1);
            cp16(sw + (wk0 * NPAD + wn0) * 4, wbase + (size_t)(k0 + wk0) * NC + wn0);
            cp16(sw + (wk1 * NPAD + wn1) * 4, wbase + (size_t)(k0 + wk1) * NC + wn1);
            cp_commit();
            cp_wait<1>();
        } else {
            cp_wait<0>();
        }
        __syncthreads();

        const float* as = As[cur];
        const float* ws = Ws[cur];
        #pragma unroll
        for (int kk = 0; kk < BK; kk += 8) {
            float a[4][4];
            float b[4][2];
            #pragma unroll
            for (int i = 0; i < 4; i++) {
                int m = wm * 64 + i * 16 + qr;
                a[i][0] = as[m * KPAD + kk + qc];
                a[i][1] = as[(m + 8) * KPAD + kk + qc];
                a[i][2] = as[m * KPAD + kk + 4 + qc];
                a[i][3] = as[(m + 8) * KPAD + kk + 4 + qc];
            }
            #pragma unroll
            for (int j = 0; j < 4; j++) {
                int n = wn * 32 + j * 8 + qr;
                b[j][0] = ws[(kk + qc) * NPAD + n];
                b[j][1] = ws[(kk + 4 + qc) * NPAD + n];
            }
            #pragma unroll
            for (int i = 0; i < 4; i++)
                #pragma unroll
                for (int j = 0; j < 4; j++)
                    mma_tf32(acc[i][j], a[i], b[j]);
        }
        __syncthreads();
    }

    // ---------------- epilogue: bias (+gelu +rna) + store ----------------
    #pragma unroll
    for (int i = 0; i < 4; i++) {
        #pragma unroll
        for (int half = 0; half < 2; half++) {
            int m = m0 + wm * 64 + i * 16 + half * 8 + qr;
            size_t crow;
            if (C_IDX) crow = xrow_off(m, e);
            else       crow = ((size_t)e * MMTOK + m) * (size_t)NC;
            #pragma unroll
            for (int j = 0; j < 4; j++) {
                int n = n0 + wn * 32 + j * 8 + qc * 2;
                float2 bv = *(const float2*)(bias + (size_t)e * NC + n);
                float vx = acc[i][j][half * 2 + 0] + bv.x;
                float vy = acc[i][j][half * 2 + 1] + bv.y;
                if (GELU) {
                    vx = rna_tf32(gelu_tanh(vx));   // rounded so GEMM2 truncation is exact
                    vy = rna_tf32(gelu_tanh(vy));
                }
                float2 o; o.x = vx; o.y = vy;
                *(float2*)(C + crow + n) = o;
            }
        }
    }
}

// ---------------- host ----------------
extern "C" void kernel_launch(void* const* d_in, const int* in_sizes, int n_in,
                              void* d_out, int out_size)
{
    const float* x  = (const float*)d_in[0];   // (B,E,N,D)
    const float* w1 = (const float*)d_in[1];   // (E,D,H)
    const float* b1 = (const float*)d_in[2];   // (E,H)
    const float* w2 = (const float*)d_in[3];   // (E,H,D)
    const float* b2 = (const float*)d_in[4];   // (E,D)
    float* out = (float*)d_out;                // (B,E,N,D)

    void *ph, *pxr, *pw1, *pw2;
    cudaGetSymbolAddress(&ph,  g_h);
    cudaGetSymbolAddress(&pxr, g_xr);
    cudaGetSymbolAddress(&pw1, g_w1r);
    cudaGetSymbolAddress(&pw2, g_w2r);
    float* h   = (float*)ph;
    float* xr  = (float*)pxr;
    float* w1r = (float*)pw1;
    float* w2r = (float*)pw2;

    // prep: unbiased tf32 rounding of inputs/weights
    {
        size_t nx = (size_t)BBATCH * EE * NTOK * DD / 4;   // float4 count
        size_t nw = (size_t)EE * DD * HH / 4;
        round_copy<<<(unsigned)(nx / 256), 256>>>(x,  xr);
        round_copy<<<(unsigned)(nw / 256), 256>>>(w1, w1r);
        round_copy<<<(unsigned)(nw / 256), 256>>>(w2, w2r);
    }

    // GEMM1: h = rna(gelu(x @ w1 + b1))
    ffn_gemm<DD, HH, true, false, true>
        <<<dim3(HH / BN, MMTOK / BM, EE), 256>>>(xr, w1r, b1, h);
    // GEMM2: out = h @ w2 + b2
    ffn_gemm<HH, DD, false, true, false>
        <<<dim3(DD / BN, MMTOK / BM, EE), 256>>>(h, w2r, b2, out);
}

// round 4
// speedup vs baseline: 6.2182x; 2.0045x over previous
#include <cuda_runtime.h>
#include <cuda_fp16.h>
#include <math.h>
#include <stdint.h>

// ---------------- problem constants ----------------
#define BBATCH 4
#define EE 8
#define NTOK 1024
#define DD 1024
#define HH 4096
#define MMTOK 4096          // B*N rows per expert

// ---------------- tile config ----------------
#define BM 128
#define BN 128
#define BK 32               // halves per k-chunk (64 B rows)
#define APAD 40             // A smem row stride in halves (80 B) - ldmatrix conflict-free
#define WPAD 136            // W smem row stride in halves (272 B) - ldmatrix.trans conflict-free

// ---------------- device scratch (fp16 copies + hidden acts) ----------------
__device__ __align__(1024) __half g_h  [(size_t)EE * MMTOK * HH];          // 256 MiB
__device__ __align__(1024) __half g_xh [(size_t)BBATCH * EE * NTOK * DD];  // 64 MiB
__device__ __align__(1024) __half g_w1h[(size_t)EE * DD * HH];             // 64 MiB
__device__ __align__(1024) __half g_w2h[(size_t)EE * HH * DD];             // 64 MiB

// ---------------- helpers ----------------
__device__ __forceinline__ float gelu_tanh(float v) {
    const float c0 = 0.7978845608028654f;
    const float c1 = 0.044715f;
    float u = c0 * (v + c1 * v * v * v);
    return 0.5f * v * (1.0f + tanhf(u));
}
__device__ __forceinline__ size_t xrow_off(int m, int e) {
    return ((size_t)((m >> 10) * EE + e) * NTOK + (size_t)(m & (NTOK - 1))) * DD;
}
__device__ __forceinline__ void cp16(uint32_t smem_dst, const void* gsrc) {
    asm volatile("cp.async.cg.shared.global [%0], [%1], 16;" :: "r"(smem_dst), "l"(gsrc));
}
__device__ __forceinline__ void cp_commit() { asm volatile("cp.async.commit_group;"); }
template<int N> __device__ __forceinline__ void cp_wait() {
    asm volatile("cp.async.wait_group %0;" :: "n"(N));
}
__device__ __forceinline__ void ldmA(uint32_t* r, uint32_t addr) {
    asm volatile("ldmatrix.sync.aligned.m8n8.x4.shared.b16 {%0,%1,%2,%3}, [%4];"
                 : "=r"(r[0]), "=r"(r[1]), "=r"(r[2]), "=r"(r[3]) : "r"(addr));
}
__device__ __forceinline__ void ldmB(uint32_t* r, uint32_t addr) {
    asm volatile("ldmatrix.sync.aligned.m8n8.x2.trans.shared.b16 {%0,%1}, [%2];"
                 : "=r"(r[0]), "=r"(r[1]) : "r"(addr));
}
__device__ __forceinline__ void mma16816(float* c, const uint32_t* a, const uint32_t* b) {
    asm volatile(
        "mma.sync.aligned.m16n8k16.row.col.f32.f16.f16.f32 "
        "{%0,%1,%2,%3}, {%4,%5,%6,%7}, {%8,%9}, {%0,%1,%2,%3};"
        : "+f"(c[0]), "+f"(c[1]), "+f"(c[2]), "+f"(c[3])
        : "r"(a[0]), "r"(a[1]), "r"(a[2]), "r"(a[3]), "r"(b[0]), "r"(b[1]));
}

// ---------------- prep: fp32 -> fp16 (RN) copy ----------------
__global__ __launch_bounds__(256) void to_half(const float4* __restrict__ in,
                                               __half2* __restrict__ out) {
    size_t i = (size_t)blockIdx.x * blockDim.x + threadIdx.x;
    float4 v = in[i];
    out[2 * i]     = __floats2half2_rn(v.x, v.y);
    out[2 * i + 1] = __floats2half2_rn(v.z, v.w);
}

// ---------------- main GEMM ----------------
// C[e] = act(A[e] @ W[e] + bias[e])
//   A: [M=4096, K] fp16 K-major. A_IDX -> x layout, else contiguous per expert.
//   W: [K, NC] fp16 row-major per expert.
//   C: half (GEMM1 -> h) or float (GEMM2 -> out); C_IDX -> (B,E,N,D) layout.
template<int K, int NC, bool A_IDX, bool C_IDX, bool GELU, class CT>
__global__ void __launch_bounds__(256, 2) ffn_gemm(
    const __half* __restrict__ A,
    const __half* __restrict__ W,
    const float* __restrict__ bias,
    CT* __restrict__ C)
{
    __shared__ __half As[2][BM * APAD];    // [m][k]
    __shared__ __half Ws[2][BK * WPAD];    // [k][n]

    const int tid  = threadIdx.x;
    const int lane = tid & 31;
    const int wid  = tid >> 5;
    const int wm   = wid >> 2;             // 0..1  (64 rows each)
    const int wn   = wid & 3;              // 0..3  (32 cols each)
    const int qr   = lane >> 2;            // 0..7
    const int qc   = lane & 3;             // 0..3

    const int e  = blockIdx.z;
    const int m0 = blockIdx.y * BM;
    const int n0 = blockIdx.x * BN;

    // ---- cp.async geometry: A = 128 rows x 4 chunks(16B); W = 32 rows x 16 chunks ----
    int ar0 = tid >> 2,        ak0 = (tid & 3) << 3;          // k offset in halves
    int ar1 = (tid + 256) >> 2, ak1 = ((tid + 256) & 3) << 3;
    size_t aoff0, aoff1;
    if (A_IDX) { aoff0 = xrow_off(m0 + ar0, e); aoff1 = xrow_off(m0 + ar1, e); }
    else       { aoff0 = ((size_t)e * MMTOK + m0 + ar0) * (size_t)K;
                 aoff1 = ((size_t)e * MMTOK + m0 + ar1) * (size_t)K; }
    int wk0 = tid >> 4,         wn0 = (tid & 15) << 3;
    int wk1 = (tid + 256) >> 4, wn1 = ((tid + 256) & 15) << 3;
    const __half* wbase = W + (size_t)e * K * NC + n0;

    uint32_t sA[2] = { (uint32_t)__cvta_generic_to_shared(&As[0][0]),
                       (uint32_t)__cvta_generic_to_shared(&As[1][0]) };
    uint32_t sW[2] = { (uint32_t)__cvta_generic_to_shared(&Ws[0][0]),
                       (uint32_t)__cvta_generic_to_shared(&Ws[1][0]) };

    // ---- ldmatrix per-lane base offsets (in halves) ----
    const int matQ = lane >> 3;            // 0..3
    const int rowQ = lane & 7;
    // A x4: mat0 rows m..m+7 k0-7 | mat1 rows m+8.. k0-7 | mat2 rows m.. k8-15 | mat3 rows m+8.. k8-15
    const int a_lane_off = (wm * 64 + (matQ & 1) * 8 + rowQ) * APAD + (matQ >> 1) * 8;
    // B x2.trans: lanes 0-7 -> k rows kk..kk+7 ; lanes 8-15 -> kk+8..kk+15 ; col n0w
    const int b_lane_off = ((matQ & 1) * 8 + rowQ) * WPAD + wn * 32;

    float acc[4][4][4];
    #pragma unroll
    for (int i = 0; i < 4; i++)
        #pragma unroll
        for (int j = 0; j < 4; j++)
            #pragma unroll
            for (int r = 0; r < 4; r++) acc[i][j][r] = 0.0f;

    constexpr int KCH = K / BK;

    // prefetch stage 0
    {
        cp16(sA[0] + (uint32_t)(ar0 * APAD + ak0) * 2, A + aoff0 + ak0);
        cp16(sA[0] + (uint32_t)(ar1 * APAD + ak1) * 2, A + aoff1 + ak1);
        cp16(sW[0] + (uint32_t)(wk0 * WPAD + wn0) * 2, wbase + (size_t)wk0 * NC + wn0);
        cp16(sW[0] + (uint32_t)(wk1 * WPAD + wn1) * 2, wbase + (size_t)wk1 * NC + wn1);
        cp_commit();
    }

    #pragma unroll 1
    for (int c = 0; c < KCH; c++) {
        const int cur = c & 1;
        if (c + 1 < KCH) {
            const int nxt = cur ^ 1;
            const int k0 = (c + 1) * BK;
            cp16(sA[nxt] + (uint32_t)(ar0 * APAD + ak0) * 2, A + aoff0 + k0 + ak0);
            cp16(sA[nxt] + (uint32_t)(ar1 * APAD + ak1) * 2, A + aoff1 + k0 + ak1);
            cp16(sW[nxt] + (uint32_t)(wk0 * WPAD + wn0) * 2, wbase + (size_t)(k0 + wk0) * NC + wn0);
            cp16(sW[nxt] + (uint32_t)(wk1 * WPAD + wn1) * 2, wbase + (size_t)(k0 + wk1) * NC + wn1);
            cp_commit();
            cp_wait<1>();
        } else {
            cp_wait<0>();
        }
        __syncthreads();

        const uint32_t asb = sA[cur];
        const uint32_t wsb = sW[cur];
        #pragma unroll
        for (int kk = 0; kk < BK; kk += 16) {
            uint32_t a[4][4];
            uint32_t b[4][2];
            #pragma unroll
            for (int i = 0; i < 4; i++)
                ldmA(a[i], asb + (uint32_t)(a_lane_off + i * 16 * APAD + kk) * 2);
            #pragma unroll
            for (int j = 0; j < 4; j++)
                ldmB(b[j], wsb + (uint32_t)(b_lane_off + kk * WPAD + j * 8) * 2);
            #pragma unroll
            for (int i = 0; i < 4; i++)
                #pragma unroll
                for (int j = 0; j < 4; j++)
                    mma16816(acc[i][j], a[i], b[j]);
        }
        __syncthreads();
    }

    // ---------------- epilogue: bias (+gelu) + store ----------------
    #pragma unroll
    for (int i = 0; i < 4; i++) {
        #pragma unroll
        for (int hh = 0; hh < 2; hh++) {
            int m = m0 + wm * 64 + i * 16 + hh * 8 + qr;
            size_t crow;
            if (C_IDX) crow = xrow_off(m, e);
            else       crow = ((size_t)e * MMTOK + m) * (size_t)NC;
            #pragma unroll
            for (int j = 0; j < 4; j++) {
                int n = n0 + wn * 32 + j * 8 + qc * 2;
                float2 bv = *(const float2*)(bias + (size_t)e * NC + n);
                float vx = acc[i][j][hh * 2 + 0] + bv.x;
                float vy = acc[i][j][hh * 2 + 1] + bv.y;
                if (GELU) { vx = gelu_tanh(vx); vy = gelu_tanh(vy); }
                if constexpr (sizeof(CT) == 2) {
                    *(__half2*)((__half*)C + crow + n) = __floats2half2_rn(vx, vy);
                } else {
                    float2 o; o.x = vx; o.y = vy;
                    *(float2*)((float*)C + crow + n) = o;
                }
            }
        }
    }
}

// ---------------- host ----------------
extern "C" void kernel_launch(void* const* d_in, const int* in_sizes, int n_in,
                              void* d_out, int out_size)
{
    const float* x  = (const float*)d_in[0];   // (B,E,N,D)
    const float* w1 = (const float*)d_in[1];   // (E,D,H)
    const float* b1 = (const float*)d_in[2];   // (E,H)
    const float* w2 = (const float*)d_in[3];   // (E,H,D)
    const float* b2 = (const float*)d_in[4];   // (E,D)
    float* out = (float*)d_out;                // (B,E,N,D)

    void *ph, *pxh, *pw1, *pw2;
    cudaGetSymbolAddress(&ph,  g_h);
    cudaGetSymbolAddress(&pxh, g_xh);
    cudaGetSymbolAddress(&pw1, g_w1h);
    cudaGetSymbolAddress(&pw2, g_w2h);
    __half* h   = (__half*)ph;
    __half* xh  = (__half*)pxh;
    __half* w1h = (__half*)pw1;
    __half* w2h = (__half*)pw2;

    // prep: fp16 conversion (RN)
    {
        size_t nx = (size_t)BBATCH * EE * NTOK * DD / 4;   // float4 count
        size_t nw = (size_t)EE * DD * HH / 4;
        to_half<<<(unsigned)(nx / 256), 256>>>((const float4*)x,  (__half2*)xh);
        to_half<<<(unsigned)(nw / 256), 256>>>((const float4*)w1, (__half2*)w1h);
        to_half<<<(unsigned)(nw / 256), 256>>>((const float4*)w2, (__half2*)w2h);
    }

    // GEMM1: h = fp16(gelu(x @ w1 + b1))
    ffn_gemm<DD, HH, true, false, true, __half>
        <<<dim3(HH / BN, MMTOK / BM, EE), 256>>>(xh, w1h, b1, h);
    // GEMM2: out = h @ w2 + b2
    ffn_gemm<HH, DD, false, true, false, float>
        <<<dim3(DD / BN, MMTOK / BM, EE), 256>>>(h, w2h, b2, out);
}

// round 5
// speedup vs baseline: 6.8391x; 1.0999x over previous
#include <cuda_runtime.h>
#include <cuda_fp16.h>
#include <math.h>
#include <stdint.h>

// ---------------- problem constants ----------------
#define BBATCH 4
#define EE 8
#define NTOK 1024
#define DD 1024
#define HH 4096
#define MMTOK 4096          // B*N rows per expert

// ---------------- tile config ----------------
#define BM 128
#define BN 128
#define BK 32               // halves per k-chunk (64 B rows)
#define STAGES 3
#define APAD 40             // A smem row stride in halves (80 B)  - ldmatrix conflict-free
#define WPAD 136            // W smem row stride in halves (272 B) - ldmatrix.trans conflict-free

// ---------------- device scratch (fp16 copies + hidden acts) ----------------
__device__ __align__(1024) __half g_h  [(size_t)EE * MMTOK * HH];          // 256 MiB
__device__ __align__(1024) __half g_xh [(size_t)BBATCH * EE * NTOK * DD];  // 64 MiB
__device__ __align__(1024) __half g_w1h[(size_t)EE * DD * HH];             // 64 MiB
__device__ __align__(1024) __half g_w2h[(size_t)EE * HH * DD];             // 64 MiB

// ---------------- helpers ----------------
__device__ __forceinline__ float gelu_tanh(float v) {
    const float c0 = 0.7978845608028654f;
    const float c1 = 0.044715f;
    float u = c0 * (v + c1 * v * v * v);
    return 0.5f * v * (1.0f + tanhf(u));
}
__device__ __forceinline__ size_t xrow_off(int m, int e) {
    return ((size_t)((m >> 10) * EE + e) * NTOK + (size_t)(m & (NTOK - 1))) * DD;
}
__device__ __forceinline__ void cp16(uint32_t smem_dst, const void* gsrc) {
    asm volatile("cp.async.cg.shared.global [%0], [%1], 16;" :: "r"(smem_dst), "l"(gsrc));
}
__device__ __forceinline__ void cp_commit() { asm volatile("cp.async.commit_group;"); }
template<int N> __device__ __forceinline__ void cp_wait() {
    asm volatile("cp.async.wait_group %0;" :: "n"(N));
}
__device__ __forceinline__ void ldmA(uint32_t* r, uint32_t addr) {
    asm volatile("ldmatrix.sync.aligned.m8n8.x4.shared.b16 {%0,%1,%2,%3}, [%4];"
                 : "=r"(r[0]), "=r"(r[1]), "=r"(r[2]), "=r"(r[3]) : "r"(addr));
}
__device__ __forceinline__ void ldmB4(uint32_t* r, uint32_t addr) {
    asm volatile("ldmatrix.sync.aligned.m8n8.x4.trans.shared.b16 {%0,%1,%2,%3}, [%4];"
                 : "=r"(r[0]), "=r"(r[1]), "=r"(r[2]), "=r"(r[3]) : "r"(addr));
}
__device__ __forceinline__ void mma16816(float* c, const uint32_t* a, const uint32_t* b) {
    asm volatile(
        "mma.sync.aligned.m16n8k16.row.col.f32.f16.f16.f32 "
        "{%0,%1,%2,%3}, {%4,%5,%6,%7}, {%8,%9}, {%0,%1,%2,%3};"
        : "+f"(c[0]), "+f"(c[1]), "+f"(c[2]), "+f"(c[3])
        : "r"(a[0]), "r"(a[1]), "r"(a[2]), "r"(a[3]), "r"(b[0]), "r"(b[1]));
}

// ---------------- prep: fp32 -> fp16 (RN) copy ----------------
__global__ __launch_bounds__(256) void to_half(const float4* __restrict__ in,
                                               __half2* __restrict__ out) {
    size_t i = (size_t)blockIdx.x * blockDim.x + threadIdx.x;
    float4 v = in[i];
    out[2 * i]     = __floats2half2_rn(v.x, v.y);
    out[2 * i + 1] = __floats2half2_rn(v.z, v.w);
}

// ---------------- main GEMM ----------------
// C[e] = act(A[e] @ W[e] + bias[e])
template<int K, int NC, bool A_IDX, bool C_IDX, bool GELU, class CT>
__global__ void __launch_bounds__(256, 2) ffn_gemm(
    const __half* __restrict__ A,
    const __half* __restrict__ W,
    const float* __restrict__ bias,
    CT* __restrict__ C)
{
    __shared__ __half As[STAGES][BM * APAD];    // [m][k]
    __shared__ __half Ws[STAGES][BK * WPAD];    // [k][n]

    const int tid  = threadIdx.x;
    const int lane = tid & 31;
    const int wid  = tid >> 5;
    const int wm   = wid >> 2;             // 0..1  (64 rows)
    const int wn   = wid & 3;              // 0..3  (32 cols)
    const int qr   = lane >> 2;            // 0..7
    const int qc   = lane & 3;             // 0..3

    const int e  = blockIdx.z;
    const int m0 = blockIdx.y * BM;
    const int n0 = blockIdx.x * BN;

    // ---- cp.async geometry ----
    int ar0 = tid >> 2,         ak0 = (tid & 3) << 3;
    int ar1 = (tid + 256) >> 2, ak1 = ((tid + 256) & 3) << 3;
    size_t aoff0, aoff1;
    if (A_IDX) { aoff0 = xrow_off(m0 + ar0, e); aoff1 = xrow_off(m0 + ar1, e); }
    else       { aoff0 = ((size_t)e * MMTOK + m0 + ar0) * (size_t)K;
                 aoff1 = ((size_t)e * MMTOK + m0 + ar1) * (size_t)K; }
    int wk0 = tid >> 4,         wn0 = (tid & 15) << 3;
    int wk1 = (tid + 256) >> 4, wn1 = ((tid + 256) & 15) << 3;
    const __half* wbase = W + (size_t)e * K * NC + n0;

    uint32_t sA[STAGES], sWb[STAGES];
    #pragma unroll
    for (int s = 0; s < STAGES; s++) {
        sA[s]  = (uint32_t)__cvta_generic_to_shared(&As[s][0]);
        sWb[s] = (uint32_t)__cvta_generic_to_shared(&Ws[s][0]);
    }

    // ---- ldmatrix per-lane base offsets (in halves) ----
    const int matQ = lane >> 3;
    const int rowQ = lane & 7;
    // A x4: {m..m+7,k0-7} {m+8..,k0-7} {m..,k8-15} {m+8..,k8-15}
    const int a_lane_off = (wm * 64 + (matQ & 1) * 8 + rowQ) * APAD + (matQ >> 1) * 8;
    // B x4.trans: {kk..+7,n_j} {kk+8..+15,n_j} {kk..+7,n_j+8} {kk+8..+15,n_j+8}
    const int b_lane_off = ((matQ & 1) * 8 + rowQ) * WPAD + wn * 32 + (matQ >> 1) * 8;

    float acc[4][4][4];
    #pragma unroll
    for (int i = 0; i < 4; i++)
        #pragma unroll
        for (int j = 0; j < 4; j++)
            #pragma unroll
            for (int r = 0; r < 4; r++) acc[i][j][r] = 0.0f;

    constexpr int KCH = K / BK;

    auto issue_stage = [&](int c, int s) {
        const int k0 = c * BK;
        cp16(sA[s]  + (uint32_t)(ar0 * APAD + ak0) * 2, A + aoff0 + k0 + ak0);
        cp16(sA[s]  + (uint32_t)(ar1 * APAD + ak1) * 2, A + aoff1 + k0 + ak1);
        cp16(sWb[s] + (uint32_t)(wk0 * WPAD + wn0) * 2, wbase + (size_t)(k0 + wk0) * NC + wn0);
        cp16(sWb[s] + (uint32_t)(wk1 * WPAD + wn1) * 2, wbase + (size_t)(k0 + wk1) * NC + wn1);
    };

    // prefetch stages 0,1
    issue_stage(0, 0); cp_commit();
    issue_stage(1, 1); cp_commit();

    int s = 0;
    #pragma unroll 1
    for (int c = 0; c < KCH; c++) {
        cp_wait<1>();             // stage s (chunk c) resident
        __syncthreads();          // all warps done with the stage we are about to overwrite

        if (c + 2 < KCH) issue_stage(c + 2, (s + 2 >= STAGES) ? s + 2 - STAGES : s + 2);
        cp_commit();              // keep one group per iteration (empty near the tail)

        const uint32_t asb = sA[s];
        const uint32_t wsb = sWb[s];
        #pragma unroll
        for (int kk = 0; kk < BK; kk += 16) {
            uint32_t a[4][4];
            uint32_t b[2][4];
            #pragma unroll
            for (int i = 0; i < 4; i++)
                ldmA(a[i], asb + (uint32_t)(a_lane_off + i * 16 * APAD + kk) * 2);
            #pragma unroll
            for (int j = 0; j < 2; j++)
                ldmB4(b[j], wsb + (uint32_t)(b_lane_off + kk * WPAD + j * 16) * 2);
            #pragma unroll
            for (int i = 0; i < 4; i++)
                #pragma unroll
                for (int j = 0; j < 4; j++)
                    mma16816(acc[i][j], a[i], &b[j >> 1][(j & 1) * 2]);
        }
        if (++s == STAGES) s = 0;
    }

    // ---------------- epilogue: bias (+gelu) + store ----------------
    #pragma unroll
    for (int i = 0; i < 4; i++) {
        #pragma unroll
        for (int hh = 0; hh < 2; hh++) {
            int m = m0 + wm * 64 + i * 16 + hh * 8 + qr;
            size_t crow;
            if (C_IDX) crow = xrow_off(m, e);
            else       crow = ((size_t)e * MMTOK + m) * (size_t)NC;
            #pragma unroll
            for (int j = 0; j < 4; j++) {
                int n = n0 + wn * 32 + j * 8 + qc * 2;
                float2 bv = *(const float2*)(bias + (size_t)e * NC + n);
                float vx = acc[i][j][hh * 2 + 0] + bv.x;
                float vy = acc[i][j][hh * 2 + 1] + bv.y;
                if (GELU) { vx = gelu_tanh(vx); vy = gelu_tanh(vy); }
                if constexpr (sizeof(CT) == 2) {
                    *(__half2*)((__half*)C + crow + n) = __floats2half2_rn(vx, vy);
                } else {
                    float2 o; o.x = vx; o.y = vy;
                    *(float2*)((float*)C + crow + n) = o;
                }
            }
        }
    }
}

// ---------------- host ----------------
extern "C" void kernel_launch(void* const* d_in, const int* in_sizes, int n_in,
                              void* d_out, int out_size)
{
    const float* x  = (const float*)d_in[0];   // (B,E,N,D)
    const float* w1 = (const float*)d_in[1];   // (E,D,H)
    const float* b1 = (const float*)d_in[2];   // (E,H)
    const float* w2 = (const float*)d_in[3];   // (E,H,D)
    const float* b2 = (const float*)d_in[4];   // (E,D)
    float* out = (float*)d_out;                // (B,E,N,D)

    void *ph, *pxh, *pw1, *pw2;
    cudaGetSymbolAddress(&ph,  g_h);
    cudaGetSymbolAddress(&pxh, g_xh);
    cudaGetSymbolAddress(&pw1, g_w1h);
    cudaGetSymbolAddress(&pw2, g_w2h);
    __half* h   = (__half*)ph;
    __half* xh  = (__half*)pxh;
    __half* w1h = (__half*)pw1;
    __half* w2h = (__half*)pw2;

    // prep: fp16 conversion (RN)
    {
        size_t nx = (size_t)BBATCH * EE * NTOK * DD / 4;   // float4 count
        size_t nw = (size_t)EE * DD * HH / 4;
        to_half<<<(unsigned)(nx / 256), 256>>>((const float4*)x,  (__half2*)xh);
        to_half<<<(unsigned)(nw / 256), 256>>>((const float4*)w1, (__half2*)w1h);
        to_half<<<(unsigned)(nw / 256), 256>>>((const float4*)w2, (__half2*)w2h);
    }

    // GEMM1: h = fp16(gelu(x @ w1 + b1))
    ffn_gemm<DD, HH, true, false, true, __half>
        <<<dim3(HH / BN, MMTOK / BM, EE), 256>>>(xh, w1h, b1, h);
    // GEMM2: out = h @ w2 + b2
    ffn_gemm<HH, DD, false, true, false, float>
        <<<dim3(DD / BN, MMTOK / BM, EE), 256>>>(h, w2h, b2, out);
}